// round 11
// baseline (speedup 1.0000x reference)
#include <cuda_runtime.h>
#include <cuda_fp16.h>
#include <math.h>
#include <stdint.h>

#define NPIX  16384   // 4*64*64
#define CDIM  128

// Scratch (device globals: no allocations allowed)
__device__ uint32_t g_qh[NPIX * 64];   // half2-packed q
__device__ uint32_t g_kh[NPIX * 64];   // half2-packed k
__device__ uint32_t g_vh[NPIX * 64];   // half2-packed v
__device__ uint32_t g_wpack[64 * 128]; // proj W: [kpair][n] half2(W[2kp][n],W[2kp+1][n])

// ---------------- fp16 mma helpers ----------------
__device__ __forceinline__ uint32_t packh2(float x, float y) {
    uint32_t r;
    asm("{ .reg .f16 lo, hi;\n\t"
        "cvt.rn.f16.f32 lo, %1;\n\t"
        "cvt.rn.f16.f32 hi, %2;\n\t"
        "mov.b32 %0, {lo, hi}; }"
        : "=r"(r) : "f"(x), "f"(y));
    return r;
}
__device__ __forceinline__ __half2 as_h2(uint32_t w) {
    return *(__half2*)&w;
}
__device__ __forceinline__ void mma_f16(float* d, const uint32_t* a,
                                        uint32_t b0, uint32_t b1) {
    asm volatile(
        "mma.sync.aligned.m16n8k16.row.col.f32.f16.f16.f32 "
        "{%0,%1,%2,%3}, {%4,%5,%6,%7}, {%8,%9}, {%0,%1,%2,%3};"
        : "+f"(d[0]), "+f"(d[1]), "+f"(d[2]), "+f"(d[3])
        : "r"(a[0]), "r"(a[1]), "r"(a[2]), "r"(a[3]), "r"(b0), "r"(b1));
}

// ---------------------------------------------------------------------------
// Fused QKV GEMM: one CTA computes a 64-row tile for ALL 3 slices.
// A staged once (fp32 -> half2), fragments hoisted to registers, B slices
// double-buffered (packed inline from fp32 W). 8 warps: 2 over M, 4 over N.
// Extra CTA (bm==256) packs proj weights into g_wpack concurrently.
// As32[row][kpair]  stride 68 : frag bank = 4g+t (lane id)
// Bs32[kpair][n]    stride 136: frag bank = 8t+g (perm)
// ---------------------------------------------------------------------------
#define PA2 68
#define PB2 136
#define QKV_SMEM ((64 * PA2 + 2 * 64 * PB2) * 4)   // 87040 B

__global__ __launch_bounds__(256) void gemm_qkv(
    const float* __restrict__ x,       // [16384, 128]
    const float* __restrict__ wq,      // [128, 384]
    const float* __restrict__ wp,      // [128, 128]
    const float* __restrict__ bias)    // [384]
{
    const int bm  = blockIdx.x;
    const int tid = threadIdx.x;

    // ---- Weight-pack CTA: pack proj W into g_wpack, run concurrently
    if (bm == 256) {
        for (int i = tid; i < 64 * 128; i += 256) {
            int kp = i >> 7;
            int n  = i & 127;
            g_wpack[i] = packh2(wp[(size_t)(2 * kp) * 128 + n],
                                wp[(size_t)(2 * kp + 1) * 128 + n]);
        }
        return;
    }

    extern __shared__ uint32_t smem_g[];
    uint32_t* As32 = smem_g;                         // [64][PA2]
    uint32_t* Bb0  = smem_g + 64 * PA2;              // [64][PB2]
    uint32_t* Bb1  = smem_g + 64 * PA2 + 64 * PB2;

    const int lane = tid & 31;
    const int wrp  = tid >> 5;
    const int g    = lane >> 2;
    const int t    = lane & 3;
    const int wm   = wrp & 1;
    const int wn   = wrp >> 1;

    // ---- Stage A: 64 rows x 128 k -> half2 pairs
    #pragma unroll
    for (int i = 0; i < 8; i++) {
        int f4 = tid + i * 256;
        int r  = f4 >> 5;
        int c4 = f4 & 31;
        float4 v = *(const float4*)&x[(size_t)(bm * 64 + r) * 128 + c4 * 4];
        As32[r * PA2 + c4 * 2 + 0] = packh2(v.x, v.y);
        As32[r * PA2 + c4 * 2 + 1] = packh2(v.z, v.w);
    }
    // ---- Stage B slice 0 into buf0 (inline fp32 -> half2 k-pair pack)
    #pragma unroll
    for (int i = 0; i < 8; i++) {
        int idx = tid + i * 256;
        int kp  = idx >> 5;
        int ng  = idx & 31;
        float4 r0 = *(const float4*)&wq[(size_t)(2 * kp)     * 384 + ng * 4];
        float4 r1 = *(const float4*)&wq[(size_t)(2 * kp + 1) * 384 + ng * 4];
        uint4 p;
        p.x = packh2(r0.x, r1.x);
        p.y = packh2(r0.y, r1.y);
        p.z = packh2(r0.z, r1.z);
        p.w = packh2(r0.w, r1.w);
        *(uint4*)&Bb0[kp * PB2 + ng * 4] = p;
    }
    __syncthreads();

    // ---- Hoist A fragments: 8 k-steps x 8 regs (reused across 3 slices)
    uint32_t afr[8][2][4];
    #pragma unroll
    for (int ks = 0; ks < 8; ks++) {
        const int kp0 = ks * 8;
        #pragma unroll
        for (int mi = 0; mi < 2; mi++) {
            int rb = wm * 32 + mi * 16;
            afr[ks][mi][0] = As32[(rb + g)     * PA2 + kp0 + t];
            afr[ks][mi][1] = As32[(rb + g + 8) * PA2 + kp0 + t];
            afr[ks][mi][2] = As32[(rb + g)     * PA2 + kp0 + 4 + t];
            afr[ks][mi][3] = As32[(rb + g + 8) * PA2 + kp0 + 4 + t];
        }
    }

    #pragma unroll
    for (int s = 0; s < 3; s++) {
        // Prefetch-stage next slice into the other buffer (WAR safe: the
        // buffer being written was last read before the sync ending s-1).
        if (s < 2) {
            uint32_t* Bn = ((s + 1) & 1) ? Bb1 : Bb0;
            #pragma unroll
            for (int i = 0; i < 8; i++) {
                int idx = tid + i * 256;
                int kp  = idx >> 5;
                int ng  = idx & 31;
                float4 r0 = *(const float4*)&wq[(size_t)(2 * kp)     * 384 + (s + 1) * 128 + ng * 4];
                float4 r1 = *(const float4*)&wq[(size_t)(2 * kp + 1) * 384 + (s + 1) * 128 + ng * 4];
                uint4 p;
                p.x = packh2(r0.x, r1.x);
                p.y = packh2(r0.y, r1.y);
                p.z = packh2(r0.z, r1.z);
                p.w = packh2(r0.w, r1.w);
                *(uint4*)&Bn[kp * PB2 + ng * 4] = p;
            }
        }

        const uint32_t* Bc = (s & 1) ? Bb1 : Bb0;
        float acc[2][4][4];
        #pragma unroll
        for (int i = 0; i < 2; i++)
            #pragma unroll
            for (int j = 0; j < 4; j++)
                #pragma unroll
                for (int c = 0; c < 4; c++) acc[i][j][c] = 0.f;

        #pragma unroll
        for (int ks = 0; ks < 8; ks++) {
            const int kp0 = ks * 8;
            #pragma unroll
            for (int ni = 0; ni < 4; ni++) {
                int cb = wn * 32 + ni * 8;
                uint32_t b0 = Bc[(kp0 + t)     * PB2 + cb + g];
                uint32_t b1 = Bc[(kp0 + 4 + t) * PB2 + cb + g];
                mma_f16(acc[0][ni], afr[ks][0], b0, b1);
                mma_f16(acc[1][ni], afr[ks][1], b0, b1);
            }
        }

        // Epilogue for slice s
        const float scale = (s == 0) ? 0.17677669529663688f : 1.0f;
        uint32_t* gd = (s == 0) ? g_qh : (s == 1) ? g_kh : g_vh;
        #pragma unroll
        for (int ni = 0; ni < 4; ni++) {
            int c  = wn * 32 + ni * 8 + t * 2;
            float b0 = bias[s * 128 + c];
            float b1 = bias[s * 128 + c + 1];
            #pragma unroll
            for (int mi = 0; mi < 2; mi++) {
                int r0 = bm * 64 + wm * 32 + mi * 16 + g;
                gd[(size_t)r0 * 64       + (c >> 1)] =
                    packh2((acc[mi][ni][0] + b0) * scale, (acc[mi][ni][1] + b1) * scale);
                gd[(size_t)(r0 + 8) * 64 + (c >> 1)] =
                    packh2((acc[mi][ni][2] + b0) * scale, (acc[mi][ni][3] + b1) * scale);
            }
        }

        if (s < 2) __syncthreads();
    }
}

// ---------------------------------------------------------------------------
// Fused neighborhood attention + output projection (unchanged from R10,
// g_wpack now holds only the proj slice).
// ---------------------------------------------------------------------------
#define NSTRIDE4 17                          // uint4 per neighbor row (68 u32)
#define KV_U32   (196 * 68)                  // 13328 u32 = 53312 B per tensor
#define NAT_SMEM (2 * KV_U32 * 4)            // 106624 B

__global__ __launch_bounds__(256, 2) void natten_proj_kernel(
    const float* __restrict__ rpb,
    const float* __restrict__ b_proj,
    float* __restrict__ out)
{
    extern __shared__ uint32_t smn[];
    uint4* Ks4 = (uint4*)smn;
    uint4* Vs4 = (uint4*)(smn + KV_U32);
    uint32_t* AT32 = smn;                    // reuses K region after pass 1
    uint32_t* BP32 = smn + KV_U32;           // reuses V region after pass 2

    const int tid  = threadIdx.x;
    const int tile = blockIdx.x & 63;
    const int b    = blockIdx.x >> 6;
    const int Y    = (tile >> 3) * 8;
    const int X    = (tile & 7) * 8;

    const int hb = min(max(Y - 3, 0), 50);
    const int wb = min(max(X - 3, 0), 50);

    // Stage K and V halos (half2-packed): 196 neighbors x 16 uint4 each
    {
        const uint4* gk4 = (const uint4*)g_kh;
        const uint4* gv4 = (const uint4*)g_vh;
        for (int i = tid; i < 196 * 16; i += 256) {
            int nb = i >> 4;
            int j  = i & 15;
            int ny = nb / 14;
            int nx = nb - ny * 14;
            int gp = (b * 64 + hb + ny) * 64 + wb + nx;
            Ks4[nb * NSTRIDE4 + j] = gk4[gp * 16 + j];
            Vs4[nb * NSTRIDE4 + j] = gv4[gp * 16 + j];
        }
    }

    const int px    = tid & 63;
    const int head  = tid >> 6;
    const int py    = px >> 3;
    const int pxx   = px & 7;
    const int y     = Y + py;
    const int x     = X + pxx;
    const int pixel = (b * 64 + y) * 64 + x;

    const int sh = min(max(y - 3, 0), 57);
    const int sw = min(max(x - 3, 0), 57);
    const int ry = sh - hb;
    const int rx = sw - wb;
    const int bias_base = head * 169 + (sh - y + 6) * 13 + (sw - x + 6);

    // q in registers: 16 half2 (overlaps with staging)
    uint32_t qw[16];
    {
        const uint4* gq4 = (const uint4*)g_qh;
        #pragma unroll
        for (int j = 0; j < 4; j++) {
            uint4 v = gq4[pixel * 16 + head * 4 + j];
            qw[j * 4 + 0] = v.x; qw[j * 4 + 1] = v.y;
            qw[j * 4 + 2] = v.z; qw[j * 4 + 3] = v.w;
        }
    }
    __syncthreads();

    // Pass 1: scores via HFMA2
    float s[49];
    #pragma unroll
    for (int iy = 0; iy < 7; iy++) {
        #pragma unroll
        for (int ix = 0; ix < 7; ix++) {
            int nb = (ry + iy) * 14 + (rx + ix);
            const uint4* kp4 = &Ks4[nb * NSTRIDE4 + head * 4];
            __half2 a0 = __float2half2_rn(0.f), a1 = a0, a2 = a0, a3 = a0;
            #pragma unroll
            for (int j = 0; j < 4; j++) {
                uint4 kv = kp4[j];
                a0 = __hfma2(as_h2(qw[j * 4 + 0]), as_h2(kv.x), a0);
                a1 = __hfma2(as_h2(qw[j * 4 + 1]), as_h2(kv.y), a1);
                a2 = __hfma2(as_h2(qw[j * 4 + 2]), as_h2(kv.z), a2);
                a3 = __hfma2(as_h2(qw[j * 4 + 3]), as_h2(kv.w), a3);
            }
            a0 = __hadd2(a0, a1);
            a2 = __hadd2(a2, a3);
            float2 f = __half22float2(__hadd2(a0, a2));
            s[iy * 7 + ix] = f.x + f.y + __ldg(&rpb[bias_base + iy * 13 + ix]);
        }
    }
    __syncthreads();   // all K reads done (K region may be overwritten below)

    // softmax in registers
    float m = s[0];
    #pragma unroll
    for (int i = 1; i < 49; i++) m = fmaxf(m, s[i]);
    float l = 0.f;
    #pragma unroll
    for (int i = 0; i < 49; i++) { s[i] = __expf(s[i] - m); l += s[i]; }
    const float inv_l = 1.0f / l;

    // Pass 2: attn @ V (fp32 accumulate from half V)
    float2 acc[16];
    #pragma unroll
    for (int i = 0; i < 16; i++) acc[i] = make_float2(0.f, 0.f);

    #pragma unroll
    for (int iy = 0; iy < 7; iy++) {
        #pragma unroll
        for (int ix = 0; ix < 7; ix++) {
            const float p = s[iy * 7 + ix];
            int nb = (ry + iy) * 14 + (rx + ix);
            const uint4* vp4 = &Vs4[nb * NSTRIDE4 + head * 4];
            #pragma unroll
            for (int j = 0; j < 4; j++) {
                uint4 vv = vp4[j];
                float2 f0 = __half22float2(as_h2(vv.x));
                float2 f1 = __half22float2(as_h2(vv.y));
                float2 f2 = __half22float2(as_h2(vv.z));
                float2 f3 = __half22float2(as_h2(vv.w));
                acc[j*4+0].x += p * f0.x; acc[j*4+0].y += p * f0.y;
                acc[j*4+1].x += p * f1.x; acc[j*4+1].y += p * f1.y;
                acc[j*4+2].x += p * f2.x; acc[j*4+2].y += p * f2.y;
                acc[j*4+3].x += p * f3.x; acc[j*4+3].y += p * f3.y;
            }
        }
    }

    // Write attention output into K region as fp16 A-tile: AT32[row][kpair]
    #pragma unroll
    for (int i = 0; i < 16; i++) {
        AT32[px * PA2 + head * 16 + i] = packh2(acc[i].x * inv_l, acc[i].y * inv_l);
    }
    __syncthreads();   // attout complete AND all V reads done

    // Stage W_proj into V region: BP32[kpair][n], stride 136
    {
        const uint4* wp4 = (const uint4*)g_wpack;
        uint4* Bp4 = (uint4*)BP32;
        #pragma unroll
        for (int i = 0; i < 8; i++) {
            int idx = tid + i * 256;
            int kp  = idx >> 5;
            int ng  = idx & 31;
            Bp4[kp * 34 + ng] = wp4[kp * 32 + ng];
        }
    }
    __syncthreads();

    // Proj GEMM: 64x128 = AT(64x128) @ Wp(128x128). 8 warps, warp tile 32x32.
    {
        const int lane = tid & 31;
        const int wrp  = tid >> 5;
        const int g    = lane >> 2;
        const int t    = lane & 3;
        const int wm   = wrp & 1;
        const int wn   = wrp >> 1;

        float pacc[2][4][4];
        #pragma unroll
        for (int i = 0; i < 2; i++)
            #pragma unroll
            for (int j = 0; j < 4; j++)
                #pragma unroll
                for (int c = 0; c < 4; c++) pacc[i][j][c] = 0.f;

        #pragma unroll
        for (int ks = 0; ks < 8; ks++) {
            const int kp0 = ks * 8;
            uint32_t a[2][4];
            #pragma unroll
            for (int mi = 0; mi < 2; mi++) {
                int rb = wm * 32 + mi * 16;
                a[mi][0] = AT32[(rb + g)     * PA2 + kp0 + t];
                a[mi][1] = AT32[(rb + g + 8) * PA2 + kp0 + t];
                a[mi][2] = AT32[(rb + g)     * PA2 + kp0 + 4 + t];
                a[mi][3] = AT32[(rb + g + 8) * PA2 + kp0 + 4 + t];
            }
            #pragma unroll
            for (int ni = 0; ni < 4; ni++) {
                int cb = wn * 32 + ni * 8;
                uint32_t b0 = BP32[(kp0 + t)     * PB2 + cb + g];
                uint32_t b1 = BP32[(kp0 + 4 + t) * PB2 + cb + g];
                mma_f16(pacc[0][ni], a[0], b0, b1);
                mma_f16(pacc[1][ni], a[1], b0, b1);
            }
        }

        // Epilogue: map local row -> pixel, add bias, store fp32
        #pragma unroll
        for (int ni = 0; ni < 4; ni++) {
            int c  = wn * 32 + ni * 8 + t * 2;
            float b0 = __ldg(&b_proj[c]);
            float b1 = __ldg(&b_proj[c + 1]);
            #pragma unroll
            for (int mi = 0; mi < 2; mi++) {
                int r = wm * 32 + mi * 16 + g;
                int p0 = (b * 64 + Y + (r >> 3)) * 64 + X + (r & 7);
                int r1 = r + 8;
                int p1 = (b * 64 + Y + (r1 >> 3)) * 64 + X + (r1 & 7);
                *(float2*)&out[(size_t)p0 * 128 + c] =
                    make_float2(pacc[mi][ni][0] + b0, pacc[mi][ni][1] + b1);
                *(float2*)&out[(size_t)p1 * 128 + c] =
                    make_float2(pacc[mi][ni][2] + b0, pacc[mi][ni][3] + b1);
            }
        }
    }
}

// ---------------------------------------------------------------------------
extern "C" void kernel_launch(void* const* d_in, const int* in_sizes, int n_in,
                              void* d_out, int out_size)
{
    const float* x      = (const float*)d_in[0];
    const float* w_qkv  = (const float*)d_in[1];
    const float* b_qkv  = (const float*)d_in[2];
    const float* rpb    = (const float*)d_in[3];
    const float* w_proj = (const float*)d_in[4];
    const float* b_proj = (const float*)d_in[5];
    float* out = (float*)d_out;

    cudaFuncSetAttribute(natten_proj_kernel,
                         cudaFuncAttributeMaxDynamicSharedMemorySize, NAT_SMEM);
    cudaFuncSetAttribute(gemm_qkv,
                         cudaFuncAttributeMaxDynamicSharedMemorySize, QKV_SMEM);

    gemm_qkv<<<257, 256, QKV_SMEM>>>(x, w_qkv, w_proj, b_qkv);
    natten_proj_kernel<<<256, 256, NAT_SMEM>>>(rpb, b_proj, out);
}